// round 17
// baseline (speedup 1.0000x reference)
#include <cuda_runtime.h>
#include <math.h>

// ChfLoss: B=8, H=W=64, P=60. loss = (0.1/B) * sum_b ||CHF(dnn_b - gt_b)||_2
// Separable trig + conjugate symmetry (R15/R16). R17: stage 2 uses packed
// f32x2 FMA (FFMA2 via PTX fma.rn.f32x2) on a q-quad with split cos/sin
// planes; conj points move to warp 4 (off warp 3's critical path).

#define NB      8
#define HWD     64
#define PP      60
#define BPB     16                  // blocks per batch (rows 0..30, 2 per block)
#define NBLK    (NB * BPB)          // 128
#define NT      256

typedef unsigned long long u64;

__device__ __forceinline__ u64 pack2(float lo, float hi) {
    u64 r; asm("mov.b64 %0, {%1, %2};" : "=l"(r) : "f"(lo), "f"(hi)); return r;
}
__device__ __forceinline__ u64 dup2(float x) {
    u64 r; asm("mov.b64 %0, {%1, %1};" : "=l"(r) : "f"(x)); return r;
}
__device__ __forceinline__ void unpack2(u64 v, float& lo, float& hi) {
    asm("mov.b64 {%0, %1}, %2;" : "=f"(lo), "=f"(hi) : "l"(v));
}
__device__ __forceinline__ u64 fma2(u64 a, u64 b, u64 c) {
    u64 d; asm("fma.rn.f32x2 %0, %1, %2, %3;" : "=l"(d) : "l"(a), "l"(b), "l"(c));
    return d;
}

// __device__ globals = sanctioned scratch (no allocation allowed)
__device__ float    g_part[NB * 16];      // [b*16 + bt]
__device__ unsigned g_count = 0;          // completion counter (self-reset)

// Shared (floats): D 4096 | cosP 3840 | sinP 3840 | sT1 256 | A 256 = 12288
// = 48KB dynamic exactly. NO static __shared__ anywhere.
__global__ __launch_bounds__(NT) void chf_fused_kernel(const float* __restrict__ dnn,
                                                       const float* __restrict__ gt,
                                                       float* __restrict__ out) {
    extern __shared__ float sm[];
    float*  sD  = sm;                               // [w*64 + h]
    float*  sC  = sm + 4096;                        // cos plane [h*60 + q]
    float*  sS  = sm + 7936;                        // sin plane [h*60 + q]
    float2* sT1 = (float2*)(sm + 11776);            // stage-1 table [w*2 + pl]
    float2* sA  = (float2*)(sm + 12032);            // [h*2 + pl] = (Ac, As)

    const int blk = blockIdx.x;
    const int b   = blk >> 4;                       // batch
    const int bt  = blk & 15;                       // row tile: rows 2bt, 2bt+1
    const int t   = threadIdx.x;

    // ---- issue global loads FIRST (latency hides the trig table gen) ----
    const float4* d4 = (const float4*)(dnn + b * 4096);
    const float4* g4 = (const float4*)(gt  + b * 4096);
    float4 va[4], vg[4];
    #pragma unroll
    for (int k = 0; k < 4; k++) {                    // 4*256 = 1024 float4 = ALL of D
        va[k] = d4[t + k * NT];
        vg[k] = g4[t + k * NT];
    }

    // ---- trig planes (15 entries/thread) + stage-1 table (t<128: 1 more) ----
    // Ref: angle = fl(r_q * x_i) fp32, then cos/sin. Exact fp32 Cody-Waite:
    // kk = rint(a/2pi) (|kk|<=243 exact); fma(-kk, 6.28125f, a) EXACT (both
    // multiples of 2^-13, |diff|<=3.6); 2nd fma ~3e-7 rad; __sincosf ~5e-7.
    {
        const float inv2pi = 0.15915494309189535f;
        const float C1 = 6.28125f;                   // 201/32, exact
        const float C2 = 1.9353071795864769e-3f;     // 2*pi - C1
        int i = t / 60;
        int q = t - i * 60;
        #pragma unroll
        for (int k = 0; k < 15; k++) {
            float r  = (float)(q - 30) * 0.1f;       // fp32 grid, matches ref
            float x  = (float)(4 + 8 * i);           // linspace(4,508,64), exact
            float a  = r * x;                        // ref's fp32 angle
            float kk = rintf(a * inv2pi);
            float ar = fmaf(-kk, C1, a);             // exact
            ar       = fmaf(-kk, C2, ar);            // |ar| <= pi (+eps)
            float s, c;
            __sincosf(ar, &s, &c);
            sC[i * 60 + q] = c;
            sS[i * 60 + q] = s;
            q += 16; i += 4;
            if (q >= 60) { q -= 60; i += 1; }
        }
        if (t < 128) {                               // sT1[w*2+pl] = trig(r_p x_w)
            int w1  = t >> 1;
            int p1  = 2 * bt + (t & 1);
            float r  = (float)(p1 - 30) * 0.1f;
            float x  = (float)(4 + 8 * w1);
            float a  = r * x;
            float kk = rintf(a * inv2pi);
            float ar = fmaf(-kk, C1, a);
            ar       = fmaf(-kk, C2, ar);
            float s, c;
            __sincosf(ar, &s, &c);
            sT1[t] = make_float2(c, s);
        }
    }

    // ---- D = dnn - gt into shared ----
    {
        float4* sD4 = (float4*)sD;
        #pragma unroll
        for (int k = 0; k < 4; k++) {
            sD4[t + k * NT] = make_float4(va[k].x - vg[k].x, va[k].y - vg[k].y,
                                          va[k].z - vg[k].z, va[k].w - vg[k].w);
        }
    }
    __syncthreads();                                 // bar 1: sD + tables ready

    // ---- stage 1: threads 0..127: A[p, h] = sum_w trig(r_p x_w) D[h, w] ----
    if (t < 128) {
        const int pl = t >> 6;                       // uniform per warp
        const int h  = t & 63;
        float ac = 0.f, as = 0.f;
        #pragma unroll 16
        for (int w = 0; w < 64; w++) {
            float  d  = sD[w * 64 + h];      // 32 consecutive -> 1 wf
            float2 cs = sT1[w * 2 + pl];     // broadcast (w, pl uniform per warp)
            ac = fmaf(cs.x, d, ac);
            as = fmaf(cs.y, d, as);
        }
        sA[h * 2 + pl] = make_float2(ac, as);
    }
    __syncthreads();                                 // bar 2: sA ready

    // ---- stage 2 ----
    // t<120 (+dead 120..127): t = qq*8 + pl*4 + hq -> q-quad (4qq..4qq+3),
    //   row 2bt+pl, h-quarter hq; packed FFMA2, 2-level shfl combine.
    // t in [128,136): conj point (60-row, 0), sg=-1, h-quarter split (warp 4).
    float v = 0.f;
    if (t < 128) {
        const int  hq  = t & 3;
        const int  pl  = (t >> 2) & 1;
        const int  qq  = (t < 120) ? (t >> 3) : 0;   // dead lanes clamp (in-bounds)
        const int  row = 2 * bt + pl;
        const int  h0  = hq * 16;
        const float4* sC4 = (const float4*)sC;       // [h*15 + qq] = q quad
        const float4* sS4 = (const float4*)sS;
        u64 ra01 = 0, ra23 = 0, rb01 = 0, rb23 = 0;
        u64 ia01 = 0, ia23 = 0, ib01 = 0, ib23 = 0;
        #pragma unroll 16
        for (int hh = 0; hh < 16; hh++) {
            int h = h0 + hh;
            float2 a  = sA[h * 2 + pl];              // (Ac, As)
            u64 ac = dup2(a.x), as = dup2(a.y);
            float4 cq = sC4[h * 15 + qq];            // c_q0..c_q3
            float4 sq = sS4[h * 15 + qq];            // s_q0..s_q3
            u64 c01 = pack2(cq.x, cq.y), c23 = pack2(cq.z, cq.w);
            u64 s01 = pack2(sq.x, sq.y), s23 = pack2(sq.z, sq.w);
            ra01 = fma2(ac, c01, ra01); ra23 = fma2(ac, c23, ra23);
            rb01 = fma2(as, s01, rb01); rb23 = fma2(as, s23, rb23);
            ia01 = fma2(as, c01, ia01); ia23 = fma2(as, c23, ia23);
            ib01 = fma2(ac, s01, ib01); ib23 = fma2(ac, s23, ib23);
        }
        float ra0, ra1, ra2, ra3, rb0, rb1, rb2, rb3;
        float ia0, ia1, ia2, ia3, ib0, ib1, ib2, ib3;
        unpack2(ra01, ra0, ra1); unpack2(ra23, ra2, ra3);
        unpack2(rb01, rb0, rb1); unpack2(rb23, rb2, rb3);
        unpack2(ia01, ia0, ia1); unpack2(ia23, ia2, ia3);
        unpack2(ib01, ib0, ib1); unpack2(ib23, ib2, ib3);
        float re0 = ra0 - rb0, im0 = ia0 + ib0;      // sg = +1
        float re1 = ra1 - rb1, im1 = ia1 + ib1;
        float re2 = ra2 - rb2, im2 = ia2 + ib2;
        float re3 = ra3 - rb3, im3 = ia3 + ib3;
        // combine h quarters: lanes hq in low 2 bits; full warps -> full mask
        #pragma unroll
        for (int d = 1; d <= 2; d <<= 1) {
            re0 += __shfl_xor_sync(0xFFFFFFFFu, re0, d);
            im0 += __shfl_xor_sync(0xFFFFFFFFu, im0, d);
            re1 += __shfl_xor_sync(0xFFFFFFFFu, re1, d);
            im1 += __shfl_xor_sync(0xFFFFFFFFu, im1, d);
            re2 += __shfl_xor_sync(0xFFFFFFFFu, re2, d);
            im2 += __shfl_xor_sync(0xFFFFFFFFu, im2, d);
            re3 += __shfl_xor_sync(0xFFFFFFFFu, re3, d);
            im3 += __shfl_xor_sync(0xFFFFFFFFu, im3, d);
        }
        if (hq == 0 && t < 120) {
            // weights: rows 1..29: q=0 ->1, q>=1 ->2; rows 0,30: 1; row 31: 0
            bool  mid  = (row >= 1 && row <= 29);
            float base = (row <= 30) ? 1.f : 0.f;
            float whi  = mid ? 2.f : base;
            float w0   = (qq == 0) ? base : whi;
            v = w0 * fmaf(re0, re0, im0 * im0)
              + whi * (fmaf(re1, re1, im1 * im1)
                     + fmaf(re2, re2, im2 * im2)
                     + fmaf(re3, re3, im3 * im3));
        }
    } else if (t < 136) {                            // conj points, warp 4
        const int t2  = t - 128;                     // 0..7 = lanes 0..7
        const int hq  = t2 & 3;
        const int pl  = t2 >> 2;
        const int row = 2 * bt + pl;
        const int h0  = hq * 16;
        float ra = 0.f, rb = 0.f, ia = 0.f, ib = 0.f;
        #pragma unroll 16
        for (int hh = 0; hh < 16; hh++) {
            int h = h0 + hh;
            float2 a = sA[h * 2 + pl];
            float  c = sC[h * 60];                   // q = 0
            float  s = sS[h * 60];
            ra = fmaf(a.x, c, ra); rb = fmaf(a.y, s, rb);
            ia = fmaf(a.y, c, ia); ib = fmaf(a.x, s, ib);
        }
        float re = ra + rb;                          // sg = -1
        float im = ib - ia;
        re += __shfl_xor_sync(0x000000FFu, re, 1);
        re += __shfl_xor_sync(0x000000FFu, re, 2);
        im += __shfl_xor_sync(0x000000FFu, im, 1);
        im += __shfl_xor_sync(0x000000FFu, im, 2);
        if (hq == 0 && row >= 1 && row <= 29)
            v = fmaf(re, re, im * im);
    }

    // ---- block reduce: warp shfl -> sD partials (sD free since bar 2) ----
    #pragma unroll
    for (int off = 16; off > 0; off >>= 1)
        v += __shfl_down_sync(0xFFFFFFFFu, v, off);
    if ((t & 31) == 0) sD[t >> 5] = v;               // 8 warp partials
    __syncthreads();                                 // bar 3 (last barrier)

    // ---- tail: t0 publishes partial; warp 0 finalizes if last ----
    if (t < 32) {
        int last = 0;
        if (t == 0) {
            float s = ((sD[0] + sD[1]) + (sD[2] + sD[3]))
                    + ((sD[4] + sD[5]) + (sD[6] + sD[7]));
            g_part[b * 16 + bt] = s;
            __threadfence();                         // release before counter bump
            unsigned c = atomicAdd(&g_count, 1u);
            last = (c == NBLK - 1) ? 1 : 0;
            if (last) g_count = 0;                   // reset for next graph replay
        }
        last = __shfl_sync(0xFFFFFFFFu, last, 0);    // warp-0 broadcast
        if (last) {
            __threadfence();                         // acquire: all g_part visible
            float w = 0.f;
            if (t < NB) {
                const float4* gp4 = (const float4*)(g_part + t * 16);
                float s = 0.f;
                #pragma unroll
                for (int k = 0; k < 4; k++) {        // fixed order -> deterministic
                    float4 p = gp4[k];
                    s += p.x + p.y + p.z + p.w;
                }
                w = sqrtf(s);
            }
            #pragma unroll
            for (int off = 4; off > 0; off >>= 1)    // 8-lane reduce
                w += __shfl_down_sync(0xFFFFFFFFu, w, off);
            if (t == 0) out[0] = w * 0.1f / 8.0f;
        }
    }
}

// ---------------------------------------------------------------------------
extern "C" void kernel_launch(void* const* d_in, const int* in_sizes, int n_in,
                              void* d_out, int out_size) {
    (void)in_sizes; (void)n_in; (void)out_size;
    const float* dnn = (const float*)d_in[0];
    const float* gt  = (const float*)d_in[1];
    float* out = (float*)d_out;

    chf_fused_kernel<<<NBLK, NT, 12288 * sizeof(float)>>>(dnn, gt, out);
}